// round 15
// baseline (speedup 1.0000x reference)
#include <cuda_runtime.h>
#include <cuda_bf16.h>

// Problem constants
#define NN    50000
#define EE    800000
#define INC   128
#define HEADS 8
#define HID   32
#define C1    256
#define OUTC  16
#define NEG   0.2f
#define EPSV  1e-16f
#define KSPLIT 384     // [Xh|Xl|Xh] x [Wh|Wh|Wl]  (XlWl term dropped)

// ---------------- scratch ----------------
__device__ float g_xl1[NN * C1];
__device__ float g_h1 [NN * C1];
__device__ float g_as1[NN * HEADS];
__device__ float g_ad1[NN * HEADS];
__device__ float g_xl2[NN * OUTC];
__device__ float g_as2[NN];
__device__ float g_ad2[NN];
__device__ int   g_deg[NN];          // zero-init at load; re-zeroed by gemm2 each run
__device__ int   g_rowptr[NN + 1];
__device__ int   g_cursor[NN];
__device__ int   g_col[EE];
__device__ int   g_bsum[64];
__device__ __nv_bfloat16 g_a1 [NN * KSPLIT];
__device__ __nv_bfloat16 g_w1t[C1 * KSPLIT];

__device__ __forceinline__ float lrelu(float x) { return x > 0.f ? x : NEG * x; }

// ---------------- fused prep (x, W1 bf16 split) + degree histogram ----------------
__global__ void prep_hist_kernel(const float* __restrict__ x, const float* __restrict__ W1,
                                 const int* __restrict__ ei) {
    int i = blockIdx.x * blockDim.x + threadIdx.x;
    if (i < NN * INC) {
        int n = i >> 7, k = i & 127;
        float v = x[i];
        __nv_bfloat16 hi = __float2bfloat16(v);
        __nv_bfloat16 lo = __float2bfloat16(v - __bfloat162float(hi));
        __nv_bfloat16* p = g_a1 + (size_t)n * KSPLIT + k;
        p[0]   = hi;
        p[128] = lo;
        p[256] = hi;
    } else if (i < NN * INC + INC * C1) {
        int j = i - NN * INC;
        int k = j >> 8, n = j & 255;
        float v = W1[j];
        __nv_bfloat16 hi = __float2bfloat16(v);
        __nv_bfloat16 lo = __float2bfloat16(v - __bfloat162float(hi));
        __nv_bfloat16* p = g_w1t + (size_t)n * KSPLIT + k;
        p[0]   = hi;
        p[128] = hi;
        p[256] = lo;
    }
    if (i < EE) atomicAdd(&g_deg[ei[EE + i]], 1);
}

// ---------------- CSR scan (2-level parallel) + scatter ----------------
__global__ void __launch_bounds__(1024)
scan1_kernel() {
    int t = threadIdx.x, b = blockIdx.x;
    int i = b * 1024 + t;
    int lane = t & 31, wid = t >> 5;
    int d = (i < NN) ? g_deg[i] : 0;
    int v = d;
#pragma unroll
    for (int o = 1; o < 32; o <<= 1) {
        int u = __shfl_up_sync(0xffffffffu, v, o);
        if (lane >= o) v += u;
    }
    __shared__ int wsum[32];
    if (lane == 31) wsum[wid] = v;
    __syncthreads();
    if (wid == 0) {
        int w = wsum[lane];
#pragma unroll
        for (int o = 1; o < 32; o <<= 1) {
            int u = __shfl_up_sync(0xffffffffu, w, o);
            if (lane >= o) w += u;
        }
        wsum[lane] = w;
    }
    __syncthreads();
    int incl = v + (wid > 0 ? wsum[wid - 1] : 0);
    if (i < NN) g_cursor[i] = incl;
    if (t == 1023) g_bsum[b] = incl;
}

__global__ void __launch_bounds__(1024)
scan2_kernel() {
    int t = threadIdx.x, b = blockIdx.x;
    int i = b * 1024 + t;
    __shared__ int soff;
    if (t == 0) {
        int o = 0;
        for (int j = 0; j < b; j++) o += g_bsum[j];
        soff = o;
    }
    __syncthreads();
    if (i < NN) {
        int incl = g_cursor[i];
        int d = g_deg[i];
        int endp = soff + incl;
        g_rowptr[i + 1] = endp;
        g_cursor[i] = endp - d;
        if (i == 0) g_rowptr[0] = 0;
    }
}

__global__ void scatter_kernel(const int* __restrict__ ei) {
    int i = blockIdx.x * blockDim.x + threadIdx.x;
    if (i < EE) {
        int d = ei[EE + i];
        int pos = atomicAdd(&g_cursor[d], 1);
        g_col[pos] = ei[i];
    }
}

// ---------------- MMA / cp.async helpers ----------------
__device__ __forceinline__ void mma_bf16(float* d, const unsigned* a, const unsigned* b) {
    asm volatile(
        "mma.sync.aligned.m16n8k16.row.col.f32.bf16.bf16.f32 "
        "{%0,%1,%2,%3}, {%4,%5,%6,%7}, {%8,%9}, {%0,%1,%2,%3};\n"
        : "+f"(d[0]), "+f"(d[1]), "+f"(d[2]), "+f"(d[3])
        : "r"(a[0]), "r"(a[1]), "r"(a[2]), "r"(a[3]), "r"(b[0]), "r"(b[1]));
}

__device__ __forceinline__ void ldsm_x4(unsigned& r0, unsigned& r1, unsigned& r2, unsigned& r3,
                                        unsigned addr) {
    asm volatile("ldmatrix.sync.aligned.m8n8.x4.shared.b16 {%0,%1,%2,%3}, [%4];\n"
                 : "=r"(r0), "=r"(r1), "=r"(r2), "=r"(r3) : "r"(addr));
}

__device__ __forceinline__ void cp_async16(unsigned dst, const void* src) {
    asm volatile("cp.async.cg.shared.global [%0], [%1], 16;\n" :: "r"(dst), "l"(src));
}
__device__ __forceinline__ void cp_commit() { asm volatile("cp.async.commit_group;\n"); }
template<int N>
__device__ __forceinline__ void cp_wait() {
    asm volatile("cp.async.wait_group %0;\n" :: "n"(N) : "memory");
}

// ---------------- GEMM1: tensor cores, cp.async double-buffered (dynamic smem) ----------------
#define AST 72
#define A_TILE (128 * AST)
#define B_TILE (64 * AST)
#define GEMM1_SMEM ((2 * A_TILE + 2 * B_TILE) * 2)   // bytes = 55296
__global__ void __launch_bounds__(256, 2)
gemm1_mma_kernel(const float* __restrict__ attS, const float* __restrict__ attD) {
    extern __shared__ __nv_bfloat16 smem[];
    __nv_bfloat16* As = smem;
    __nv_bfloat16* Bs = smem + 2 * A_TILE;
    int tid = threadIdx.x;
    int warp = tid >> 5, lane = tid & 31;
    int wm = warp >> 1, wn = warp & 1;
    int bm = blockIdx.x * 128, bn = blockIdx.y * 64;
    int r = lane >> 2, c = lane & 3;
    int head = (bn + wn * 32) >> 5;

    float aSv[8], aDv[8];
#pragma unroll
    for (int n = 0; n < 4; n++) {
        aSv[n * 2]     = attS[head * HID + n * 8 + 2 * c];
        aSv[n * 2 + 1] = attS[head * HID + n * 8 + 2 * c + 1];
        aDv[n * 2]     = attD[head * HID + n * 8 + 2 * c];
        aDv[n * 2 + 1] = attD[head * HID + n * 8 + 2 * c + 1];
    }

    unsigned as_base = (unsigned)__cvta_generic_to_shared(As);
    unsigned bs_base = (unsigned)__cvta_generic_to_shared(Bs);
    unsigned a_off = (unsigned)(((wm * 32 + (lane & 7) + ((lane >> 3) & 1) * 8) * AST + (lane >> 4) * 8) * 2);
    unsigned b_off = (unsigned)(((wn * 32 + (lane & 7) + (lane >> 4) * 8) * AST + ((lane >> 3) & 1) * 8) * 2);

    int a_row = tid >> 3, a_c8 = (tid & 7) << 3;
    int b_row = tid >> 3, b_c8 = (tid & 7) << 3;

    auto load_tiles = [&](int k0, int buf) {
        unsigned ad = as_base + buf * A_TILE * 2;
        unsigned bd = bs_base + buf * B_TILE * 2;
#pragma unroll
        for (int it = 0; it < 4; it++) {
            int row = a_row + it * 32;
            int grow = bm + row; if (grow > NN - 1) grow = NN - 1;
            cp_async16(ad + (row * AST + a_c8) * 2,
                       g_a1 + (size_t)grow * KSPLIT + k0 + a_c8);
        }
#pragma unroll
        for (int it = 0; it < 2; it++) {
            int n = b_row + it * 32;
            cp_async16(bd + (n * AST + b_c8) * 2,
                       g_w1t + (size_t)(bn + n) * KSPLIT + k0 + b_c8);
        }
    };

    float acc[2][4][4];
#pragma unroll
    for (int m = 0; m < 2; m++)
#pragma unroll
        for (int n = 0; n < 4; n++)
#pragma unroll
            for (int j = 0; j < 4; j++) acc[m][n][j] = 0.f;

    load_tiles(0, 0);
    cp_commit();

    const int NITER = KSPLIT / 64;   // 6
    for (int i = 0; i < NITER; i++) {
        int buf = i & 1;
        if (i + 1 < NITER) {
            load_tiles((i + 1) * 64, buf ^ 1);
            cp_commit();
            cp_wait<1>();
        } else {
            cp_wait<0>();
        }
        __syncthreads();
        unsigned a_addr = as_base + buf * A_TILE * 2 + a_off;
        unsigned b_addr = bs_base + buf * B_TILE * 2 + b_off;
#pragma unroll
        for (int kk = 0; kk < 64; kk += 16) {
            unsigned af[2][4], bf[4][2];
            ldsm_x4(af[0][0], af[0][1], af[0][2], af[0][3], a_addr + kk * 2);
            ldsm_x4(af[1][0], af[1][1], af[1][2], af[1][3], a_addr + (16 * AST + kk) * 2);
            ldsm_x4(bf[0][0], bf[0][1], bf[1][0], bf[1][1], b_addr + kk * 2);
            ldsm_x4(bf[2][0], bf[2][1], bf[3][0], bf[3][1], b_addr + (16 * AST + kk) * 2);
#pragma unroll
            for (int m = 0; m < 2; m++)
#pragma unroll
                for (int n = 0; n < 4; n++) mma_bf16(acc[m][n], af[m], bf[n]);
        }
        __syncthreads();
    }

    // epilogue: xl1 stores + fused attention logits
#pragma unroll
    for (int m = 0; m < 2; m++) {
        int row0 = bm + wm * 32 + m * 16 + r;
#pragma unroll
        for (int n = 0; n < 4; n++) {
            int col = bn + wn * 32 + n * 8 + 2 * c;
            if (row0 < NN)
                *(float2*)(g_xl1 + (size_t)row0 * C1 + col) = make_float2(acc[m][n][0], acc[m][n][1]);
            if (row0 + 8 < NN)
                *(float2*)(g_xl1 + (size_t)(row0 + 8) * C1 + col) = make_float2(acc[m][n][2], acc[m][n][3]);
        }
        float s0 = 0.f, s1 = 0.f, d0 = 0.f, d1 = 0.f;
#pragma unroll
        for (int n = 0; n < 4; n++) {
            s0 += acc[m][n][0] * aSv[n * 2] + acc[m][n][1] * aSv[n * 2 + 1];
            s1 += acc[m][n][2] * aSv[n * 2] + acc[m][n][3] * aSv[n * 2 + 1];
            d0 += acc[m][n][0] * aDv[n * 2] + acc[m][n][1] * aDv[n * 2 + 1];
            d1 += acc[m][n][2] * aDv[n * 2] + acc[m][n][3] * aDv[n * 2 + 1];
        }
#pragma unroll
        for (int o = 1; o <= 2; o <<= 1) {
            s0 += __shfl_xor_sync(0xffffffffu, s0, o);
            s1 += __shfl_xor_sync(0xffffffffu, s1, o);
            d0 += __shfl_xor_sync(0xffffffffu, d0, o);
            d1 += __shfl_xor_sync(0xffffffffu, d1, o);
        }
        if (c == 0) {
            if (row0 < NN)     { g_as1[row0 * HEADS + head] = s0;       g_ad1[row0 * HEADS + head] = d0; }
            if (row0 + 8 < NN) { g_as1[(row0 + 8) * HEADS + head] = s1; g_ad1[(row0 + 8) * HEADS + head] = d1; }
        }
    }
}

// ---------------- aggregation layer1: 2 warps per node, chunk-4, smem combine ----------------
// grid = 12500 blocks x 256 thr = 100000 warps = 2 per node (no early returns).
__global__ void __launch_bounds__(256)
agg1_kernel(const float* __restrict__ b1) {
    int gw = (blockIdx.x * blockDim.x + threadIdx.x) >> 5;
    int node = gw >> 1;
    int sub  = gw & 1;
    int lane = threadIdx.x & 31;
    int myh = lane >> 2;
    int l4  = lane & 3;
    int c0  = lane * 8;
    int start = g_rowptr[node];
    int end   = g_rowptr[node + 1];

    float ad = g_ad1[(size_t)node * HEADS + myh];

    float acc[8];
#pragma unroll
    for (int j = 0; j < 8; j++) acc[j] = 0.f;
    float ssum = 0.f;

    if (sub == 0) {
        float es = __expf(lrelu(g_as1[(size_t)node * HEADS + myh] + ad));
        const float4* xp = (const float4*)(g_xl1 + (size_t)node * C1 + c0);
        float4 v0 = xp[0], v1 = xp[1];
        acc[0] = es*v0.x; acc[1] = es*v0.y; acc[2] = es*v0.z; acc[3] = es*v0.w;
        acc[4] = es*v1.x; acc[5] = es*v1.y; acc[6] = es*v1.z; acc[7] = es*v1.w;
        ssum = es;
    }

    for (int base = start + sub * 4; base < end; base += 8) {
        int rem = end - base; if (rem > 4) rem = 4;          // sub-warp-uniform
        int s = g_col[base + (l4 < rem ? l4 : 0)];
        float e = (l4 < rem) ? __expf(lrelu(g_as1[(size_t)s * HEADS + myh] + ad)) : 0.f;
        int g = lane & ~3;
        float ej[4]; int sj[4];
#pragma unroll
        for (int j = 0; j < 4; j++) {
            ej[j] = __shfl_sync(0xffffffffu, e, g + j);
            sj[j] = __shfl_sync(0xffffffffu, s, g + j);
        }
        float4 v[4][2];
#pragma unroll
        for (int j = 0; j < 4; j++) {
            const float4* xp = (const float4*)(g_xl1 + (size_t)sj[j] * C1 + c0);
            v[j][0] = xp[0];
            v[j][1] = xp[1];
        }
#pragma unroll
        for (int j = 0; j < 4; j++) {
            float e_ = ej[j];
            acc[0] += e_*v[j][0].x; acc[1] += e_*v[j][0].y;
            acc[2] += e_*v[j][0].z; acc[3] += e_*v[j][0].w;
            acc[4] += e_*v[j][1].x; acc[5] += e_*v[j][1].y;
            acc[6] += e_*v[j][1].z; acc[7] += e_*v[j][1].w;
            ssum += e_;
        }
    }

    // combine the two sub-warps via smem (4 node-pairs per block)
    __shared__ float sm[4][32][10];
    int nl = threadIdx.x >> 6;                 // 0..3 node slot in block
    if (sub == 1) {
#pragma unroll
        for (int j = 0; j < 8; j++) sm[nl][lane][j] = acc[j];
        sm[nl][lane][8] = ssum;
    }
    __syncthreads();
    if (sub == 0) {
#pragma unroll
        for (int j = 0; j < 8; j++) acc[j] += sm[nl][lane][j];
        ssum += sm[nl][lane][8];

        float inv = 1.f / (ssum + EPSV);
        float ov[8];
#pragma unroll
        for (int j = 0; j < 8; j++) {
            float v = acc[j] * inv + b1[c0 + j];
            ov[j] = v > 0.f ? v : (__expf(v) - 1.f);
        }
        float4* hp = (float4*)(g_h1 + (size_t)node * C1 + c0);
        hp[0] = make_float4(ov[0], ov[1], ov[2], ov[3]);
        hp[1] = make_float4(ov[4], ov[5], ov[6], ov[7]);
    }
}

// ---------------- GEMM2: 1024 thr = 32 rows/block, W2 staged once, fused logits2 ----------------
#define W2PAD 17
__global__ void __launch_bounds__(1024)
gemm2_kernel(const float* __restrict__ W2,
             const float* __restrict__ att_s2,
             const float* __restrict__ att_d2) {
    __shared__ float Ws[256 * W2PAD];
    __shared__ float sa[16], sd[16];
    int tid = threadIdx.x;
    int warp = tid >> 5, lane = tid & 31;

    int z = blockIdx.x * 1024 + tid;
    if (z < NN) g_deg[z] = 0;                // re-zero for next replay

    for (int i = tid; i < 4096; i += 1024) {
        int k = i >> 4, c = i & 15;
        Ws[k * W2PAD + c] = W2[i];
    }
    if (tid < 16) { sa[tid] = att_s2[tid]; sd[tid] = att_d2[tid]; }
    __syncthreads();

    int row = blockIdx.x * 32 + warp;
    if (row >= NN) return;

    float4 h0 = *(const float4*)(g_h1 + (size_t)row * C1 + lane * 8);
    float4 h1 = *(const float4*)(g_h1 + (size_t)row * C1 + lane * 8 + 4);
    float hv[8] = {h0.x, h0.y, h0.z, h0.w, h1.x, h1.y, h1.z, h1.w};

    float p[16];
#pragma unroll
    for (int c = 0; c < 16; c++) p[c] = 0.f;
#pragma unroll
    for (int j = 0; j < 8; j++) {
        const float* wr = &Ws[(lane * 8 + j) * W2PAD];
        float4 w0 = *(const float4*)(wr + 0);
        float4 w1 = *(const float4*)(wr + 4);
        float4 w2 = *(const float4*)(wr + 8);
        float4 w3 = *(const float4*)(wr + 12);
        float h = hv[j];
        p[0]  += h * w0.x; p[1]  += h * w0.y; p[2]  += h * w0.z; p[3]  += h * w0.w;
        p[4]  += h * w1.x; p[5]  += h * w1.y; p[6]  += h * w1.z; p[7]  += h * w1.w;
        p[8]  += h * w2.x; p[9]  += h * w2.y; p[10] += h * w2.z; p[11] += h * w2.w;
        p[12] += h * w3.x; p[13] += h * w3.y; p[14] += h * w3.z; p[15] += h * w3.w;
    }
#pragma unroll
    for (int o = 16; o; o >>= 1)
#pragma unroll
        for (int c = 0; c < 16; c++) p[c] += __shfl_xor_sync(0xffffffffu, p[c], o);

    if (lane < 16) {
        float myv = 0.f;
#pragma unroll
        for (int c = 0; c < 16; c++) if (c == lane) myv = p[c];
        g_xl2[(size_t)row * OUTC + lane] = myv;
    }
    if (lane == 0) {
        float vs = 0.f, vd = 0.f;
#pragma unroll
        for (int c = 0; c < 16; c++) { vs += p[c] * sa[c]; vd += p[c] * sd[c]; }
        g_as2[row] = vs;
        g_ad2[row] = vd;
    }
}

// ---------------- aggregation layer2: 8 edge-slots x 4 channel-quads ----------------
__global__ void __launch_bounds__(256)
agg2_kernel(const float* __restrict__ b2, float* __restrict__ out) {
    int warp = (blockIdx.x * blockDim.x + threadIdx.x) >> 5;
    if (warp >= NN) return;
    int lane = threadIdx.x & 31;
    int node = warp;
    int start = g_rowptr[node];
    int end   = g_rowptr[node + 1];
    int slot = lane >> 2;
    int q    = lane & 3;

    float ad = g_ad2[node];
    float a0 = 0.f, a1 = 0.f, a2 = 0.f, a3 = 0.f;
    float ssum = 0.f;

    if (slot == 0) {
        float es = __expf(lrelu(g_as2[node] + ad));
        const float4 v = *(const float4*)(g_xl2 + (size_t)node * OUTC + q * 4);
        a0 = es * v.x; a1 = es * v.y; a2 = es * v.z; a3 = es * v.w;
        if (q == 0) ssum = es;
    }

    for (int base = start; base < end; base += 8) {
        int rem = end - base;
        int s = g_col[base + (slot < rem ? slot : 0)];
        float e = 0.f;
        if (q == 0 && slot < rem) e = __expf(lrelu(g_as2[s] + ad));
        e = __shfl_sync(0xffffffffu, e, lane & ~3);
        const float4 v = *(const float4*)(g_xl2 + (size_t)s * OUTC + q * 4);
        a0 += e * v.x; a1 += e * v.y; a2 += e * v.z; a3 += e * v.w;
        if (q == 0) ssum += e;
    }

#pragma unroll
    for (int o = 4; o <= 16; o <<= 1) {
        a0 += __shfl_xor_sync(0xffffffffu, a0, o);
        a1 += __shfl_xor_sync(0xffffffffu, a1, o);
        a2 += __shfl_xor_sync(0xffffffffu, a2, o);
        a3 += __shfl_xor_sync(0xffffffffu, a3, o);
        ssum += __shfl_xor_sync(0xffffffffu, ssum, o);
    }
    float tot = __shfl_sync(0xffffffffu, ssum, 0);
    if (lane < 4) {
        float inv = 1.f / (tot + EPSV);
        float4 bo = *(const float4*)(b2 + q * 4);
        float4 res = make_float4(a0 * inv + bo.x, a1 * inv + bo.y,
                                 a2 * inv + bo.z, a3 * inv + bo.w);
        *(float4*)(out + (size_t)node * OUTC + q * 4) = res;
    }
}

// ---------------- launch ----------------
extern "C" void kernel_launch(void* const* d_in, const int* in_sizes, int n_in,
                              void* d_out, int out_size) {
    const float* x     = (const float*)d_in[0];
    const int*   ei    = (const int*)d_in[1];
    const float* W1    = (const float*)d_in[2];
    const float* atts1 = (const float*)d_in[3];
    const float* attd1 = (const float*)d_in[4];
    const float* b1    = (const float*)d_in[5];
    const float* W2    = (const float*)d_in[6];
    const float* atts2 = (const float*)d_in[7];
    const float* attd2 = (const float*)d_in[8];
    const float* b2    = (const float*)d_in[9];
    float* out = (float*)d_out;

    cudaFuncSetAttribute(gemm1_mma_kernel,
                         cudaFuncAttributeMaxDynamicSharedMemorySize, GEMM1_SMEM);

    prep_hist_kernel<<<(NN * INC + INC * C1 + 255) / 256, 256>>>(x, W1, ei); // 0
    scan1_kernel<<<49, 1024>>>();                                            // 1
    scan2_kernel<<<49, 1024>>>();                                            // 2
    gemm1_mma_kernel<<<dim3((NN + 127) / 128, 4), 256, GEMM1_SMEM>>>(atts1, attd1); // 3 <- profiled
    scatter_kernel<<<(EE + 255) / 256, 256>>>(ei);                           // 4
    agg1_kernel<<<12500, 256>>>(b1);                                         // 5
    gemm2_kernel<<<(NN + 31) / 32, 1024>>>(W2, atts2, attd2);                // 6
    agg2_kernel<<<(NN + 7) / 8, 256>>>(b2, out);                             // 7
}

// round 16
// speedup vs baseline: 1.0356x; 1.0356x over previous
#include <cuda_runtime.h>
#include <cuda_bf16.h>

// Problem constants
#define NN    50000
#define EE    800000
#define INC   128
#define HEADS 8
#define HID   32
#define C1    256
#define OUTC  16
#define NEG   0.2f
#define EPSV  1e-16f
#define KSPLIT 384     // [Xh|Xl|Xh] x [Wh|Wh|Wl]  (XlWl term dropped)

// ---------------- scratch ----------------
__device__ float g_xl1[NN * C1];
__device__ float g_as1[NN * HEADS];
__device__ float g_ad1[NN * HEADS];
__device__ float g_xl2[NN * OUTC];
__device__ float g_as2[NN];
__device__ float g_ad2[NN];
__device__ int   g_deg[NN];          // zero-init at load; re-zeroed by agg2 each run
__device__ int   g_rowptr[NN + 1];
__device__ int   g_cursor[NN];
__device__ int   g_col[EE];
__device__ int   g_bsum[64];
__device__ __nv_bfloat16 g_a1 [NN * KSPLIT];
__device__ __nv_bfloat16 g_w1t[C1 * KSPLIT];

__device__ __forceinline__ float lrelu(float x) { return x > 0.f ? x : NEG * x; }

// ---------------- fused prep (x, W1 bf16 split) + degree histogram ----------------
__global__ void prep_hist_kernel(const float* __restrict__ x, const float* __restrict__ W1,
                                 const int* __restrict__ ei) {
    int i = blockIdx.x * blockDim.x + threadIdx.x;
    if (i < NN * INC) {
        int n = i >> 7, k = i & 127;
        float v = x[i];
        __nv_bfloat16 hi = __float2bfloat16(v);
        __nv_bfloat16 lo = __float2bfloat16(v - __bfloat162float(hi));
        __nv_bfloat16* p = g_a1 + (size_t)n * KSPLIT + k;
        p[0]   = hi;
        p[128] = lo;
        p[256] = hi;
    } else if (i < NN * INC + INC * C1) {
        int j = i - NN * INC;
        int k = j >> 8, n = j & 255;
        float v = W1[j];
        __nv_bfloat16 hi = __float2bfloat16(v);
        __nv_bfloat16 lo = __float2bfloat16(v - __bfloat162float(hi));
        __nv_bfloat16* p = g_w1t + (size_t)n * KSPLIT + k;
        p[0]   = hi;
        p[128] = hi;
        p[256] = lo;
    }
    if (i < EE) atomicAdd(&g_deg[ei[EE + i]], 1);
}

// ---------------- CSR scan (2-level parallel) + scatter ----------------
__global__ void __launch_bounds__(1024)
scan1_kernel() {
    int t = threadIdx.x, b = blockIdx.x;
    int i = b * 1024 + t;
    int lane = t & 31, wid = t >> 5;
    int d = (i < NN) ? g_deg[i] : 0;
    int v = d;
#pragma unroll
    for (int o = 1; o < 32; o <<= 1) {
        int u = __shfl_up_sync(0xffffffffu, v, o);
        if (lane >= o) v += u;
    }
    __shared__ int wsum[32];
    if (lane == 31) wsum[wid] = v;
    __syncthreads();
    if (wid == 0) {
        int w = wsum[lane];
#pragma unroll
        for (int o = 1; o < 32; o <<= 1) {
            int u = __shfl_up_sync(0xffffffffu, w, o);
            if (lane >= o) w += u;
        }
        wsum[lane] = w;
    }
    __syncthreads();
    int incl = v + (wid > 0 ? wsum[wid - 1] : 0);
    if (i < NN) g_cursor[i] = incl;
    if (t == 1023) g_bsum[b] = incl;
}

__global__ void __launch_bounds__(1024)
scan2_kernel() {
    int t = threadIdx.x, b = blockIdx.x;
    int i = b * 1024 + t;
    __shared__ int soff;
    if (t == 0) {
        int o = 0;
        for (int j = 0; j < b; j++) o += g_bsum[j];
        soff = o;
    }
    __syncthreads();
    if (i < NN) {
        int incl = g_cursor[i];
        int d = g_deg[i];
        int endp = soff + incl;
        g_rowptr[i + 1] = endp;
        g_cursor[i] = endp - d;
        if (i == 0) g_rowptr[0] = 0;
    }
}

__global__ void scatter_kernel(const int* __restrict__ ei) {
    int i = blockIdx.x * blockDim.x + threadIdx.x;
    if (i < EE) {
        int d = ei[EE + i];
        int pos = atomicAdd(&g_cursor[d], 1);
        g_col[pos] = ei[i];
    }
}

// ---------------- MMA / cp.async helpers ----------------
__device__ __forceinline__ void mma_bf16(float* d, const unsigned* a, const unsigned* b) {
    asm volatile(
        "mma.sync.aligned.m16n8k16.row.col.f32.bf16.bf16.f32 "
        "{%0,%1,%2,%3}, {%4,%5,%6,%7}, {%8,%9}, {%0,%1,%2,%3};\n"
        : "+f"(d[0]), "+f"(d[1]), "+f"(d[2]), "+f"(d[3])
        : "r"(a[0]), "r"(a[1]), "r"(a[2]), "r"(a[3]), "r"(b[0]), "r"(b[1]));
}

__device__ __forceinline__ void ldsm_x4(unsigned& r0, unsigned& r1, unsigned& r2, unsigned& r3,
                                        unsigned addr) {
    asm volatile("ldmatrix.sync.aligned.m8n8.x4.shared.b16 {%0,%1,%2,%3}, [%4];\n"
                 : "=r"(r0), "=r"(r1), "=r"(r2), "=r"(r3) : "r"(addr));
}

__device__ __forceinline__ void cp_async16(unsigned dst, const void* src) {
    asm volatile("cp.async.cg.shared.global [%0], [%1], 16;\n" :: "r"(dst), "l"(src));
}
__device__ __forceinline__ void cp_commit() { asm volatile("cp.async.commit_group;\n"); }
template<int N>
__device__ __forceinline__ void cp_wait() {
    asm volatile("cp.async.wait_group %0;\n" :: "n"(N) : "memory");
}

// ---------------- GEMM1: tensor cores, cp.async double-buffered (dynamic smem) ----------------
#define AST 72
#define A_TILE (128 * AST)
#define B_TILE (64 * AST)
#define GEMM1_SMEM ((2 * A_TILE + 2 * B_TILE) * 2)   // bytes = 55296
__global__ void __launch_bounds__(256, 2)
gemm1_mma_kernel(const float* __restrict__ attS, const float* __restrict__ attD) {
    extern __shared__ __nv_bfloat16 smem[];
    __nv_bfloat16* As = smem;
    __nv_bfloat16* Bs = smem + 2 * A_TILE;
    int tid = threadIdx.x;
    int warp = tid >> 5, lane = tid & 31;
    int wm = warp >> 1, wn = warp & 1;
    int bm = blockIdx.x * 128, bn = blockIdx.y * 64;
    int r = lane >> 2, c = lane & 3;
    int head = (bn + wn * 32) >> 5;

    float aSv[8], aDv[8];
#pragma unroll
    for (int n = 0; n < 4; n++) {
        aSv[n * 2]     = attS[head * HID + n * 8 + 2 * c];
        aSv[n * 2 + 1] = attS[head * HID + n * 8 + 2 * c + 1];
        aDv[n * 2]     = attD[head * HID + n * 8 + 2 * c];
        aDv[n * 2 + 1] = attD[head * HID + n * 8 + 2 * c + 1];
    }

    unsigned as_base = (unsigned)__cvta_generic_to_shared(As);
    unsigned bs_base = (unsigned)__cvta_generic_to_shared(Bs);
    unsigned a_off = (unsigned)(((wm * 32 + (lane & 7) + ((lane >> 3) & 1) * 8) * AST + (lane >> 4) * 8) * 2);
    unsigned b_off = (unsigned)(((wn * 32 + (lane & 7) + (lane >> 4) * 8) * AST + ((lane >> 3) & 1) * 8) * 2);

    int a_row = tid >> 3, a_c8 = (tid & 7) << 3;
    int b_row = tid >> 3, b_c8 = (tid & 7) << 3;

    auto load_tiles = [&](int k0, int buf) {
        unsigned ad = as_base + buf * A_TILE * 2;
        unsigned bd = bs_base + buf * B_TILE * 2;
#pragma unroll
        for (int it = 0; it < 4; it++) {
            int row = a_row + it * 32;
            int grow = bm + row; if (grow > NN - 1) grow = NN - 1;
            cp_async16(ad + (row * AST + a_c8) * 2,
                       g_a1 + (size_t)grow * KSPLIT + k0 + a_c8);
        }
#pragma unroll
        for (int it = 0; it < 2; it++) {
            int n = b_row + it * 32;
            cp_async16(bd + (n * AST + b_c8) * 2,
                       g_w1t + (size_t)(bn + n) * KSPLIT + k0 + b_c8);
        }
    };

    float acc[2][4][4];
#pragma unroll
    for (int m = 0; m < 2; m++)
#pragma unroll
        for (int n = 0; n < 4; n++)
#pragma unroll
            for (int j = 0; j < 4; j++) acc[m][n][j] = 0.f;

    load_tiles(0, 0);
    cp_commit();

    const int NITER = KSPLIT / 64;   // 6
    for (int i = 0; i < NITER; i++) {
        int buf = i & 1;
        if (i + 1 < NITER) {
            load_tiles((i + 1) * 64, buf ^ 1);
            cp_commit();
            cp_wait<1>();
        } else {
            cp_wait<0>();
        }
        __syncthreads();
        unsigned a_addr = as_base + buf * A_TILE * 2 + a_off;
        unsigned b_addr = bs_base + buf * B_TILE * 2 + b_off;
#pragma unroll
        for (int kk = 0; kk < 64; kk += 16) {
            unsigned af[2][4], bf[4][2];
            ldsm_x4(af[0][0], af[0][1], af[0][2], af[0][3], a_addr + kk * 2);
            ldsm_x4(af[1][0], af[1][1], af[1][2], af[1][3], a_addr + (16 * AST + kk) * 2);
            ldsm_x4(bf[0][0], bf[0][1], bf[1][0], bf[1][1], b_addr + kk * 2);
            ldsm_x4(bf[2][0], bf[2][1], bf[3][0], bf[3][1], b_addr + (16 * AST + kk) * 2);
#pragma unroll
            for (int m = 0; m < 2; m++)
#pragma unroll
                for (int n = 0; n < 4; n++) mma_bf16(acc[m][n], af[m], bf[n]);
        }
        __syncthreads();
    }

    // epilogue: xl1 stores + fused attention logits
#pragma unroll
    for (int m = 0; m < 2; m++) {
        int row0 = bm + wm * 32 + m * 16 + r;
#pragma unroll
        for (int n = 0; n < 4; n++) {
            int col = bn + wn * 32 + n * 8 + 2 * c;
            if (row0 < NN)
                *(float2*)(g_xl1 + (size_t)row0 * C1 + col) = make_float2(acc[m][n][0], acc[m][n][1]);
            if (row0 + 8 < NN)
                *(float2*)(g_xl1 + (size_t)(row0 + 8) * C1 + col) = make_float2(acc[m][n][2], acc[m][n][3]);
        }
        float s0 = 0.f, s1 = 0.f, d0 = 0.f, d1 = 0.f;
#pragma unroll
        for (int n = 0; n < 4; n++) {
            s0 += acc[m][n][0] * aSv[n * 2] + acc[m][n][1] * aSv[n * 2 + 1];
            s1 += acc[m][n][2] * aSv[n * 2] + acc[m][n][3] * aSv[n * 2 + 1];
            d0 += acc[m][n][0] * aDv[n * 2] + acc[m][n][1] * aDv[n * 2 + 1];
            d1 += acc[m][n][2] * aDv[n * 2] + acc[m][n][3] * aDv[n * 2 + 1];
        }
#pragma unroll
        for (int o = 1; o <= 2; o <<= 1) {
            s0 += __shfl_xor_sync(0xffffffffu, s0, o);
            s1 += __shfl_xor_sync(0xffffffffu, s1, o);
            d0 += __shfl_xor_sync(0xffffffffu, d0, o);
            d1 += __shfl_xor_sync(0xffffffffu, d1, o);
        }
        if (c == 0) {
            if (row0 < NN)     { g_as1[row0 * HEADS + head] = s0;       g_ad1[row0 * HEADS + head] = d0; }
            if (row0 + 8 < NN) { g_as1[(row0 + 8) * HEADS + head] = s1; g_ad1[(row0 + 8) * HEADS + head] = d1; }
        }
    }
}

// ---------------- agg1 + fused GEMM2/logits2: warp per node ----------------
// After aggregating h (post-ELU, post-bias) in registers, each warp directly
// computes xl2 = h @ W2 (warp-per-row dot) and the layer-2 logits.
#define W2PAD 17
__global__ void __launch_bounds__(256)
agg1_kernel(const float* __restrict__ b1, const float* __restrict__ W2,
            const float* __restrict__ att_s2, const float* __restrict__ att_d2) {
    __shared__ float Ws[256 * W2PAD];   // W2 [k][16] padded
    __shared__ float sa[16], sd[16];
    int tid = threadIdx.x;
    for (int i = tid; i < 4096; i += 256) {
        int k = i >> 4, c = i & 15;
        Ws[k * W2PAD + c] = W2[i];
    }
    if (tid < 16) { sa[tid] = att_s2[tid]; sd[tid] = att_d2[tid]; }
    __syncthreads();

    int warp = (blockIdx.x * blockDim.x + tid) >> 5;
    if (warp >= NN) return;
    int lane = tid & 31;
    int node = warp;
    int start = g_rowptr[node];
    int end   = g_rowptr[node + 1];
    int myh = lane >> 2;
    int l4  = lane & 3;
    int c0  = lane * 8;

    float ad = g_ad1[(size_t)node * HEADS + myh];
    float es = __expf(lrelu(g_as1[(size_t)node * HEADS + myh] + ad));

    float acc[8];
    float ssum = es;
    {
        const float4* xp = (const float4*)(g_xl1 + (size_t)node * C1 + c0);
        float4 v0 = xp[0], v1 = xp[1];
        acc[0] = es*v0.x; acc[1] = es*v0.y; acc[2] = es*v0.z; acc[3] = es*v0.w;
        acc[4] = es*v1.x; acc[5] = es*v1.y; acc[6] = es*v1.z; acc[7] = es*v1.w;
    }

    for (int base = start; base < end; base += 4) {
        int rem = end - base; if (rem > 4) rem = 4;
        int s = g_col[base + (l4 < rem ? l4 : 0)];
        float e = (l4 < rem) ? __expf(lrelu(g_as1[(size_t)s * HEADS + myh] + ad)) : 0.f;
        int g = lane & ~3;
        float ej[4]; int sj[4];
#pragma unroll
        for (int j = 0; j < 4; j++) {
            ej[j] = __shfl_sync(0xffffffffu, e, g + j);
            sj[j] = __shfl_sync(0xffffffffu, s, g + j);
        }
        float4 v[4][2];
#pragma unroll
        for (int j = 0; j < 4; j++) {
            const float4* xp = (const float4*)(g_xl1 + (size_t)sj[j] * C1 + c0);
            v[j][0] = xp[0];
            v[j][1] = xp[1];
        }
#pragma unroll
        for (int j = 0; j < 4; j++) {
            float e_ = ej[j];
            acc[0] += e_*v[j][0].x; acc[1] += e_*v[j][0].y;
            acc[2] += e_*v[j][0].z; acc[3] += e_*v[j][0].w;
            acc[4] += e_*v[j][1].x; acc[5] += e_*v[j][1].y;
            acc[6] += e_*v[j][1].z; acc[7] += e_*v[j][1].w;
            ssum += e_;
        }
    }
    float inv = 1.f / (ssum + EPSV);
    float hv[8];
#pragma unroll
    for (int j = 0; j < 8; j++) {
        float v = acc[j] * inv + b1[c0 + j];
        hv[j] = v > 0.f ? v : (__expf(v) - 1.f);     // h row element (post-ELU)
    }

    // fused GEMM2: p[c] = sum_k h[k] * W2[k][c]; lane owns k in [c0, c0+8)
    float p[16];
#pragma unroll
    for (int c = 0; c < 16; c++) p[c] = 0.f;
#pragma unroll
    for (int j = 0; j < 8; j++) {
        const float* wr = &Ws[(c0 + j) * W2PAD];
        float4 w0 = *(const float4*)(wr + 0);
        float4 w1 = *(const float4*)(wr + 4);
        float4 w2 = *(const float4*)(wr + 8);
        float4 w3 = *(const float4*)(wr + 12);
        float h = hv[j];
        p[0]  += h * w0.x; p[1]  += h * w0.y; p[2]  += h * w0.z; p[3]  += h * w0.w;
        p[4]  += h * w1.x; p[5]  += h * w1.y; p[6]  += h * w1.z; p[7]  += h * w1.w;
        p[8]  += h * w2.x; p[9]  += h * w2.y; p[10] += h * w2.z; p[11] += h * w2.w;
        p[12] += h * w3.x; p[13] += h * w3.y; p[14] += h * w3.z; p[15] += h * w3.w;
    }
#pragma unroll
    for (int o = 16; o; o >>= 1)
#pragma unroll
        for (int c = 0; c < 16; c++) p[c] += __shfl_xor_sync(0xffffffffu, p[c], o);

    if (lane < 16) {
        float myv = 0.f;
#pragma unroll
        for (int c = 0; c < 16; c++) if (c == lane) myv = p[c];
        g_xl2[(size_t)node * OUTC + lane] = myv;
    }
    if (lane == 0) {
        float vs = 0.f, vd = 0.f;
#pragma unroll
        for (int c = 0; c < 16; c++) { vs += p[c] * sa[c]; vd += p[c] * sd[c]; }
        g_as2[node] = vs;
        g_ad2[node] = vd;
    }
}

// ---------------- aggregation layer2: 8 edge-slots x 4 channel-quads + deg re-zero ----------------
__global__ void __launch_bounds__(256)
agg2_kernel(const float* __restrict__ b2, float* __restrict__ out) {
    int gtid = blockIdx.x * blockDim.x + threadIdx.x;
    for (int z = gtid; z < NN; z += gridDim.x * blockDim.x)
        g_deg[z] = 0;                                   // re-zero for next replay

    int warp = gtid >> 5;
    if (warp >= NN) return;
    int lane = threadIdx.x & 31;
    int node = warp;
    int start = g_rowptr[node];
    int end   = g_rowptr[node + 1];
    int slot = lane >> 2;
    int q    = lane & 3;

    float ad = g_ad2[node];
    float a0 = 0.f, a1 = 0.f, a2 = 0.f, a3 = 0.f;
    float ssum = 0.f;

    if (slot == 0) {
        float es = __expf(lrelu(g_as2[node] + ad));
        const float4 v = *(const float4*)(g_xl2 + (size_t)node * OUTC + q * 4);
        a0 = es * v.x; a1 = es * v.y; a2 = es * v.z; a3 = es * v.w;
        if (q == 0) ssum = es;
    }

    for (int base = start; base < end; base += 8) {
        int rem = end - base;
        int s = g_col[base + (slot < rem ? slot : 0)];
        float e = 0.f;
        if (q == 0 && slot < rem) e = __expf(lrelu(g_as2[s] + ad));
        e = __shfl_sync(0xffffffffu, e, lane & ~3);
        const float4 v = *(const float4*)(g_xl2 + (size_t)s * OUTC + q * 4);
        a0 += e * v.x; a1 += e * v.y; a2 += e * v.z; a3 += e * v.w;
        if (q == 0) ssum += e;
    }

#pragma unroll
    for (int o = 4; o <= 16; o <<= 1) {
        a0 += __shfl_xor_sync(0xffffffffu, a0, o);
        a1 += __shfl_xor_sync(0xffffffffu, a1, o);
        a2 += __shfl_xor_sync(0xffffffffu, a2, o);
        a3 += __shfl_xor_sync(0xffffffffu, a3, o);
        ssum += __shfl_xor_sync(0xffffffffu, ssum, o);
    }
    float tot = __shfl_sync(0xffffffffu, ssum, 0);
    if (lane < 4) {
        float inv = 1.f / (tot + EPSV);
        float4 bo = *(const float4*)(b2 + q * 4);
        float4 res = make_float4(a0 * inv + bo.x, a1 * inv + bo.y,
                                 a2 * inv + bo.z, a3 * inv + bo.w);
        *(float4*)(out + (size_t)node * OUTC + q * 4) = res;
    }
}

// ---------------- launch ----------------
extern "C" void kernel_launch(void* const* d_in, const int* in_sizes, int n_in,
                              void* d_out, int out_size) {
    const float* x     = (const float*)d_in[0];
    const int*   ei    = (const int*)d_in[1];
    const float* W1    = (const float*)d_in[2];
    const float* atts1 = (const float*)d_in[3];
    const float* attd1 = (const float*)d_in[4];
    const float* b1    = (const float*)d_in[5];
    const float* W2    = (const float*)d_in[6];
    const float* atts2 = (const float*)d_in[7];
    const float* attd2 = (const float*)d_in[8];
    const float* b2    = (const float*)d_in[9];
    float* out = (float*)d_out;

    cudaFuncSetAttribute(gemm1_mma_kernel,
                         cudaFuncAttributeMaxDynamicSharedMemorySize, GEMM1_SMEM);

    prep_hist_kernel<<<(NN * INC + INC * C1 + 255) / 256, 256>>>(x, W1, ei); // 0
    scan1_kernel<<<49, 1024>>>();                                            // 1
    scan2_kernel<<<49, 1024>>>();                                            // 2
    gemm1_mma_kernel<<<dim3((NN + 127) / 128, 4), 256, GEMM1_SMEM>>>(atts1, attd1); // 3 <- profiled
    scatter_kernel<<<(EE + 255) / 256, 256>>>(ei);                           // 4
    agg1_kernel<<<(NN + 7) / 8, 256>>>(b1, W2, atts2, attd2);                // 5
    agg2_kernel<<<(NN + 7) / 8, 256>>>(b2, out);                             // 6
}

// round 17
// speedup vs baseline: 1.0979x; 1.0602x over previous
#include <cuda_runtime.h>
#include <cuda_bf16.h>

// Problem constants
#define NN    50000
#define EE    800000
#define INC   128
#define HEADS 8
#define HID   32
#define C1    256
#define OUTC  16
#define NEG   0.2f
#define EPSV  1e-16f
#define KSPLIT 384     // [Xh|Xl|Xh] x [Wh|Wh|Wl]  (XlWl term dropped)

// ---------------- scratch ----------------
__device__ float g_xl1[NN * C1];
__device__ float g_as1[NN * HEADS];
__device__ float g_ad1[NN * HEADS];
__device__ float g_xl2[NN * OUTC];
__device__ float g_as2[NN];
__device__ float g_ad2[NN];
__device__ int   g_deg[NN];          // zero-init at load; re-zeroed by agg2 each run
__device__ int   g_rowptr[NN + 1];
__device__ int   g_cursor[NN];
__device__ int   g_col[EE];
__device__ int   g_bsum[64];
__device__ __nv_bfloat16 g_a1 [NN * KSPLIT];
__device__ __nv_bfloat16 g_w1t[C1 * KSPLIT];

__device__ __forceinline__ float lrelu(float x) { return x > 0.f ? x : NEG * x; }

// ---------------- fused prep (vectorized bf16 split) + degree histogram ----------------
// x part: thread per 8 k-elements (NN*16 threads). W part: 4096 threads. hist: first EE threads.
__global__ void prep_hist_kernel(const float* __restrict__ x, const float* __restrict__ W1,
                                 const int* __restrict__ ei) {
    int i = blockIdx.x * blockDim.x + threadIdx.x;
    if (i < NN * 16) {
        int n = i >> 4, k0 = (i & 15) << 3;
        const float4* xp = (const float4*)(x + (size_t)n * INC + k0);
        float4 f0 = xp[0], f1 = xp[1];
        float f[8] = {f0.x, f0.y, f0.z, f0.w, f1.x, f1.y, f1.z, f1.w};
        __nv_bfloat16 hi[8], lo[8];
#pragma unroll
        for (int j = 0; j < 8; j++) {
            hi[j] = __float2bfloat16(f[j]);
            lo[j] = __float2bfloat16(f[j] - __bfloat162float(hi[j]));
        }
        __nv_bfloat16* p = g_a1 + (size_t)n * KSPLIT + k0;
        *(uint4*)(p)       = *(uint4*)hi;
        *(uint4*)(p + 128) = *(uint4*)lo;
        *(uint4*)(p + 256) = *(uint4*)hi;
    } else if (i < NN * 16 + 4096) {
        int j = i - NN * 16;
        int n = j & 255, kb = j >> 8;      // kb 0..15
        int k0 = kb << 3;
        __nv_bfloat16 hi[8], lo[8];
#pragma unroll
        for (int t = 0; t < 8; t++) {
            float v = W1[(size_t)(k0 + t) * C1 + n];
            hi[t] = __float2bfloat16(v);
            lo[t] = __float2bfloat16(v - __bfloat162float(hi[t]));
        }
        __nv_bfloat16* p = g_w1t + (size_t)n * KSPLIT + k0;
        *(uint4*)(p)       = *(uint4*)hi;
        *(uint4*)(p + 128) = *(uint4*)hi;
        *(uint4*)(p + 256) = *(uint4*)lo;
    }
    if (i < EE) atomicAdd(&g_deg[ei[EE + i]], 1);
}

// ---------------- CSR scan (2-level parallel) + scatter ----------------
__global__ void __launch_bounds__(1024)
scan1_kernel() {
    int t = threadIdx.x, b = blockIdx.x;
    int i = b * 1024 + t;
    int lane = t & 31, wid = t >> 5;
    int d = (i < NN) ? g_deg[i] : 0;
    int v = d;
#pragma unroll
    for (int o = 1; o < 32; o <<= 1) {
        int u = __shfl_up_sync(0xffffffffu, v, o);
        if (lane >= o) v += u;
    }
    __shared__ int wsum[32];
    if (lane == 31) wsum[wid] = v;
    __syncthreads();
    if (wid == 0) {
        int w = wsum[lane];
#pragma unroll
        for (int o = 1; o < 32; o <<= 1) {
            int u = __shfl_up_sync(0xffffffffu, w, o);
            if (lane >= o) w += u;
        }
        wsum[lane] = w;
    }
    __syncthreads();
    int incl = v + (wid > 0 ? wsum[wid - 1] : 0);
    if (i < NN) g_cursor[i] = incl;
    if (t == 1023) g_bsum[b] = incl;
}

__global__ void __launch_bounds__(1024)
scan2_kernel() {
    int t = threadIdx.x, b = blockIdx.x;
    int i = b * 1024 + t;
    __shared__ int soff;
    if (t == 0) {
        int o = 0;
        for (int j = 0; j < b; j++) o += g_bsum[j];
        soff = o;
    }
    __syncthreads();
    if (i < NN) {
        int incl = g_cursor[i];
        int d = g_deg[i];
        int endp = soff + incl;
        g_rowptr[i + 1] = endp;
        g_cursor[i] = endp - d;
        if (i == 0) g_rowptr[0] = 0;
    }
}

__global__ void scatter_kernel(const int* __restrict__ ei) {
    int i = blockIdx.x * blockDim.x + threadIdx.x;
    if (i < EE) {
        int d = ei[EE + i];
        int pos = atomicAdd(&g_cursor[d], 1);
        g_col[pos] = ei[i];
    }
}

// ---------------- MMA / cp.async helpers ----------------
__device__ __forceinline__ void mma_bf16(float* d, const unsigned* a, const unsigned* b) {
    asm volatile(
        "mma.sync.aligned.m16n8k16.row.col.f32.bf16.bf16.f32 "
        "{%0,%1,%2,%3}, {%4,%5,%6,%7}, {%8,%9}, {%0,%1,%2,%3};\n"
        : "+f"(d[0]), "+f"(d[1]), "+f"(d[2]), "+f"(d[3])
        : "r"(a[0]), "r"(a[1]), "r"(a[2]), "r"(a[3]), "r"(b[0]), "r"(b[1]));
}

__device__ __forceinline__ void ldsm_x4(unsigned& r0, unsigned& r1, unsigned& r2, unsigned& r3,
                                        unsigned addr) {
    asm volatile("ldmatrix.sync.aligned.m8n8.x4.shared.b16 {%0,%1,%2,%3}, [%4];\n"
                 : "=r"(r0), "=r"(r1), "=r"(r2), "=r"(r3) : "r"(addr));
}

__device__ __forceinline__ void cp_async16(unsigned dst, const void* src) {
    asm volatile("cp.async.cg.shared.global [%0], [%1], 16;\n" :: "r"(dst), "l"(src));
}
__device__ __forceinline__ void cp_commit() { asm volatile("cp.async.commit_group;\n"); }
template<int N>
__device__ __forceinline__ void cp_wait() {
    asm volatile("cp.async.wait_group %0;\n" :: "n"(N) : "memory");
}

// ---------------- GEMM1: tensor cores, 3-stage cp.async pipeline (dynamic smem) ----------------
#define AST 72
#define A_TILE (128 * AST)
#define B_TILE (64 * AST)
#define STAGE_T (A_TILE + B_TILE)
#define GEMM1_SMEM (3 * STAGE_T * 2)     // 82944 bytes
__global__ void __launch_bounds__(256, 2)
gemm1_mma_kernel(const float* __restrict__ attS, const float* __restrict__ attD) {
    extern __shared__ __nv_bfloat16 smem[];
    int tid = threadIdx.x;
    int warp = tid >> 5, lane = tid & 31;
    int wm = warp >> 1, wn = warp & 1;
    int bm = blockIdx.x * 128, bn = blockIdx.y * 64;
    int r = lane >> 2, c = lane & 3;
    int head = (bn + wn * 32) >> 5;

    float aSv[8], aDv[8];
#pragma unroll
    for (int n = 0; n < 4; n++) {
        aSv[n * 2]     = attS[head * HID + n * 8 + 2 * c];
        aSv[n * 2 + 1] = attS[head * HID + n * 8 + 2 * c + 1];
        aDv[n * 2]     = attD[head * HID + n * 8 + 2 * c];
        aDv[n * 2 + 1] = attD[head * HID + n * 8 + 2 * c + 1];
    }

    unsigned s_base = (unsigned)__cvta_generic_to_shared(smem);
    // within a stage: A at offset 0, B at A_TILE
    unsigned a_off = (unsigned)(((wm * 32 + (lane & 7) + ((lane >> 3) & 1) * 8) * AST + (lane >> 4) * 8) * 2);
    unsigned b_off = (unsigned)(A_TILE * 2) +
        (unsigned)(((wn * 32 + (lane & 7) + (lane >> 4) * 8) * AST + ((lane >> 3) & 1) * 8) * 2);

    int a_row = tid >> 3, a_c8 = (tid & 7) << 3;

    auto load_tiles = [&](int k0, int buf) {
        unsigned sd = s_base + buf * STAGE_T * 2;
#pragma unroll
        for (int it = 0; it < 4; it++) {
            int row = a_row + it * 32;
            int grow = bm + row; if (grow > NN - 1) grow = NN - 1;
            cp_async16(sd + (row * AST + a_c8) * 2,
                       g_a1 + (size_t)grow * KSPLIT + k0 + a_c8);
        }
        unsigned bd = sd + A_TILE * 2;
#pragma unroll
        for (int it = 0; it < 2; it++) {
            int n = a_row + it * 32;
            cp_async16(bd + (n * AST + a_c8) * 2,
                       g_w1t + (size_t)(bn + n) * KSPLIT + k0 + a_c8);
        }
    };

    float acc[2][4][4];
#pragma unroll
    for (int m = 0; m < 2; m++)
#pragma unroll
        for (int n = 0; n < 4; n++)
#pragma unroll
            for (int j = 0; j < 4; j++) acc[m][n][j] = 0.f;

    load_tiles(0, 0);  cp_commit();
    load_tiles(64, 1); cp_commit();

    const int NITER = KSPLIT / 64;   // 6
    for (int i = 0; i < NITER; i++) {
        int buf = i % 3;
        if (i + 1 < NITER) cp_wait<1>(); else cp_wait<0>();
        __syncthreads();              // buf i ready; compute(i-1) retired everywhere
        if (i + 2 < NITER) {
            load_tiles((i + 2) * 64, (i + 2) % 3);
            cp_commit();
        }
        unsigned a_addr = s_base + buf * STAGE_T * 2 + a_off;
        unsigned b_addr = s_base + buf * STAGE_T * 2 + b_off;
#pragma unroll
        for (int kk = 0; kk < 64; kk += 16) {
            unsigned af[2][4], bf[4][2];
            ldsm_x4(af[0][0], af[0][1], af[0][2], af[0][3], a_addr + kk * 2);
            ldsm_x4(af[1][0], af[1][1], af[1][2], af[1][3], a_addr + (16 * AST + kk) * 2);
            ldsm_x4(bf[0][0], bf[0][1], bf[1][0], bf[1][1], b_addr + kk * 2);
            ldsm_x4(bf[2][0], bf[2][1], bf[3][0], bf[3][1], b_addr + (16 * AST + kk) * 2);
#pragma unroll
            for (int m = 0; m < 2; m++)
#pragma unroll
                for (int n = 0; n < 4; n++) mma_bf16(acc[m][n], af[m], bf[n]);
        }
    }

    // epilogue: xl1 stores + fused attention logits
#pragma unroll
    for (int m = 0; m < 2; m++) {
        int row0 = bm + wm * 32 + m * 16 + r;
#pragma unroll
        for (int n = 0; n < 4; n++) {
            int col = bn + wn * 32 + n * 8 + 2 * c;
            if (row0 < NN)
                *(float2*)(g_xl1 + (size_t)row0 * C1 + col) = make_float2(acc[m][n][0], acc[m][n][1]);
            if (row0 + 8 < NN)
                *(float2*)(g_xl1 + (size_t)(row0 + 8) * C1 + col) = make_float2(acc[m][n][2], acc[m][n][3]);
        }
        float s0 = 0.f, s1 = 0.f, d0 = 0.f, d1 = 0.f;
#pragma unroll
        for (int n = 0; n < 4; n++) {
            s0 += acc[m][n][0] * aSv[n * 2] + acc[m][n][1] * aSv[n * 2 + 1];
            s1 += acc[m][n][2] * aSv[n * 2] + acc[m][n][3] * aSv[n * 2 + 1];
            d0 += acc[m][n][0] * aDv[n * 2] + acc[m][n][1] * aDv[n * 2 + 1];
            d1 += acc[m][n][2] * aDv[n * 2] + acc[m][n][3] * aDv[n * 2 + 1];
        }
#pragma unroll
        for (int o = 1; o <= 2; o <<= 1) {
            s0 += __shfl_xor_sync(0xffffffffu, s0, o);
            s1 += __shfl_xor_sync(0xffffffffu, s1, o);
            d0 += __shfl_xor_sync(0xffffffffu, d0, o);
            d1 += __shfl_xor_sync(0xffffffffu, d1, o);
        }
        if (c == 0) {
            if (row0 < NN)     { g_as1[row0 * HEADS + head] = s0;       g_ad1[row0 * HEADS + head] = d0; }
            if (row0 + 8 < NN) { g_as1[(row0 + 8) * HEADS + head] = s1; g_ad1[(row0 + 8) * HEADS + head] = d1; }
        }
    }
}

// ---------------- agg1 + fused GEMM2/logits2: warp per node ----------------
#define W2PAD 17
__global__ void __launch_bounds__(256)
agg1_kernel(const float* __restrict__ b1, const float* __restrict__ W2,
            const float* __restrict__ att_s2, const float* __restrict__ att_d2) {
    __shared__ float Ws[256 * W2PAD];
    __shared__ float sa[16], sd[16];
    int tid = threadIdx.x;
    for (int i = tid; i < 4096; i += 256) {
        int k = i >> 4, c = i & 15;
        Ws[k * W2PAD + c] = W2[i];
    }
    if (tid < 16) { sa[tid] = att_s2[tid]; sd[tid] = att_d2[tid]; }
    __syncthreads();

    int warp = (blockIdx.x * blockDim.x + tid) >> 5;
    if (warp >= NN) return;
    int lane = tid & 31;
    int node = warp;
    int start = g_rowptr[node];
    int end   = g_rowptr[node + 1];
    int myh = lane >> 2;
    int l4  = lane & 3;
    int c0  = lane * 8;

    float ad = g_ad1[(size_t)node * HEADS + myh];
    float es = __expf(lrelu(g_as1[(size_t)node * HEADS + myh] + ad));

    float acc[8];
    float ssum = es;
    {
        const float4* xp = (const float4*)(g_xl1 + (size_t)node * C1 + c0);
        float4 v0 = xp[0], v1 = xp[1];
        acc[0] = es*v0.x; acc[1] = es*v0.y; acc[2] = es*v0.z; acc[3] = es*v0.w;
        acc[4] = es*v1.x; acc[5] = es*v1.y; acc[6] = es*v1.z; acc[7] = es*v1.w;
    }

    for (int base = start; base < end; base += 4) {
        int rem = end - base; if (rem > 4) rem = 4;
        int s = g_col[base + (l4 < rem ? l4 : 0)];
        float e = (l4 < rem) ? __expf(lrelu(g_as1[(size_t)s * HEADS + myh] + ad)) : 0.f;
        int g = lane & ~3;
        float ej[4]; int sj[4];
#pragma unroll
        for (int j = 0; j < 4; j++) {
            ej[j] = __shfl_sync(0xffffffffu, e, g + j);
            sj[j] = __shfl_sync(0xffffffffu, s, g + j);
        }
        float4 v[4][2];
#pragma unroll
        for (int j = 0; j < 4; j++) {
            const float4* xp = (const float4*)(g_xl1 + (size_t)sj[j] * C1 + c0);
            v[j][0] = xp[0];
            v[j][1] = xp[1];
        }
#pragma unroll
        for (int j = 0; j < 4; j++) {
            float e_ = ej[j];
            acc[0] += e_*v[j][0].x; acc[1] += e_*v[j][0].y;
            acc[2] += e_*v[j][0].z; acc[3] += e_*v[j][0].w;
            acc[4] += e_*v[j][1].x; acc[5] += e_*v[j][1].y;
            acc[6] += e_*v[j][1].z; acc[7] += e_*v[j][1].w;
            ssum += e_;
        }
    }
    float inv = 1.f / (ssum + EPSV);
    float hv[8];
#pragma unroll
    for (int j = 0; j < 8; j++) {
        float v = acc[j] * inv + b1[c0 + j];
        hv[j] = v > 0.f ? v : (__expf(v) - 1.f);
    }

    float p[16];
#pragma unroll
    for (int c = 0; c < 16; c++) p[c] = 0.f;
#pragma unroll
    for (int j = 0; j < 8; j++) {
        const float* wr = &Ws[(c0 + j) * W2PAD];
        float4 w0 = *(const float4*)(wr + 0);
        float4 w1 = *(const float4*)(wr + 4);
        float4 w2 = *(const float4*)(wr + 8);
        float4 w3 = *(const float4*)(wr + 12);
        float h = hv[j];
        p[0]  += h * w0.x; p[1]  += h * w0.y; p[2]  += h * w0.z; p[3]  += h * w0.w;
        p[4]  += h * w1.x; p[5]  += h * w1.y; p[6]  += h * w1.z; p[7]  += h * w1.w;
        p[8]  += h * w2.x; p[9]  += h * w2.y; p[10] += h * w2.z; p[11] += h * w2.w;
        p[12] += h * w3.x; p[13] += h * w3.y; p[14] += h * w3.z; p[15] += h * w3.w;
    }
#pragma unroll
    for (int o = 16; o; o >>= 1)
#pragma unroll
        for (int c = 0; c < 16; c++) p[c] += __shfl_xor_sync(0xffffffffu, p[c], o);

    if (lane < 16) {
        float myv = 0.f;
#pragma unroll
        for (int c = 0; c < 16; c++) if (c == lane) myv = p[c];
        g_xl2[(size_t)node * OUTC + lane] = myv;
    }
    if (lane == 0) {
        float vs = 0.f, vd = 0.f;
#pragma unroll
        for (int c = 0; c < 16; c++) { vs += p[c] * sa[c]; vd += p[c] * sd[c]; }
        g_as2[node] = vs;
        g_ad2[node] = vd;
    }
}

// ---------------- aggregation layer2: 8 edge-slots x 4 channel-quads + deg re-zero ----------------
__global__ void __launch_bounds__(256)
agg2_kernel(const float* __restrict__ b2, float* __restrict__ out) {
    int gtid = blockIdx.x * blockDim.x + threadIdx.x;
    for (int z = gtid; z < NN; z += gridDim.x * blockDim.x)
        g_deg[z] = 0;

    int warp = gtid >> 5;
    if (warp >= NN) return;
    int lane = threadIdx.x & 31;
    int node = warp;
    int start = g_rowptr[node];
    int end   = g_rowptr[node + 1];
    int slot = lane >> 2;
    int q    = lane & 3;

    float ad = g_ad2[node];
    float a0 = 0.f, a1 = 0.f, a2 = 0.f, a3 = 0.f;
    float ssum = 0.f;

    if (slot == 0) {
        float es = __expf(lrelu(g_as2[node] + ad));
        const float4 v = *(const float4*)(g_xl2 + (size_t)node * OUTC + q * 4);
        a0 = es * v.x; a1 = es * v.y; a2 = es * v.z; a3 = es * v.w;
        if (q == 0) ssum = es;
    }

    for (int base = start; base < end; base += 8) {
        int rem = end - base;
        int s = g_col[base + (slot < rem ? slot : 0)];
        float e = 0.f;
        if (q == 0 && slot < rem) e = __expf(lrelu(g_as2[s] + ad));
        e = __shfl_sync(0xffffffffu, e, lane & ~3);
        const float4 v = *(const float4*)(g_xl2 + (size_t)s * OUTC + q * 4);
        a0 += e * v.x; a1 += e * v.y; a2 += e * v.z; a3 += e * v.w;
        if (q == 0) ssum += e;
    }

#pragma unroll
    for (int o = 4; o <= 16; o <<= 1) {
        a0 += __shfl_xor_sync(0xffffffffu, a0, o);
        a1 += __shfl_xor_sync(0xffffffffu, a1, o);
        a2 += __shfl_xor_sync(0xffffffffu, a2, o);
        a3 += __shfl_xor_sync(0xffffffffu, a3, o);
        ssum += __shfl_xor_sync(0xffffffffu, ssum, o);
    }
    float tot = __shfl_sync(0xffffffffu, ssum, 0);
    if (lane < 4) {
        float inv = 1.f / (tot + EPSV);
        float4 bo = *(const float4*)(b2 + q * 4);
        float4 res = make_float4(a0 * inv + bo.x, a1 * inv + bo.y,
                                 a2 * inv + bo.z, a3 * inv + bo.w);
        *(float4*)(out + (size_t)node * OUTC + q * 4) = res;
    }
}

// ---------------- launch ----------------
extern "C" void kernel_launch(void* const* d_in, const int* in_sizes, int n_in,
                              void* d_out, int out_size) {
    const float* x     = (const float*)d_in[0];
    const int*   ei    = (const int*)d_in[1];
    const float* W1    = (const float*)d_in[2];
    const float* atts1 = (const float*)d_in[3];
    const float* attd1 = (const float*)d_in[4];
    const float* b1    = (const float*)d_in[5];
    const float* W2    = (const float*)d_in[6];
    const float* atts2 = (const float*)d_in[7];
    const float* attd2 = (const float*)d_in[8];
    const float* b2    = (const float*)d_in[9];
    float* out = (float*)d_out;

    cudaFuncSetAttribute(gemm1_mma_kernel,
                         cudaFuncAttributeMaxDynamicSharedMemorySize, GEMM1_SMEM);

    prep_hist_kernel<<<(NN * 16 + 4096 + 255) / 256, 256>>>(x, W1, ei);      // 0
    scan1_kernel<<<49, 1024>>>();                                            // 1
    scan2_kernel<<<49, 1024>>>();                                            // 2
    gemm1_mma_kernel<<<dim3((NN + 127) / 128, 4), 256, GEMM1_SMEM>>>(atts1, attd1); // 3 <- profiled
    scatter_kernel<<<(EE + 255) / 256, 256>>>(ei);                           // 4
    agg1_kernel<<<(NN + 7) / 8, 256>>>(b1, W2, atts2, attd2);                // 5
    agg2_kernel<<<(NN + 7) / 8, 256>>>(b2, out);                             // 6
}